// round 2
// baseline (speedup 1.0000x reference)
#include <cuda_runtime.h>
#include <cstdint>

#define T_TOK 2048
#define DDIM  2048
#define NOUT  11264
#define LEXP  16
#define HALF_B 5632

// ---------------- scratch (device globals: allocation-free) ----------------
__device__ __align__(16) float g_xr[(size_t)T_TOK * DDIM];   // tf32-rounded x
__device__ __align__(16) float g_wr[(size_t)NOUT * DDIM];    // tf32-rounded W
__device__ float g_xa[T_TOK * 32];                           // xa = x . A[l]
__device__ int   g_tok[T_TOK];                               // tokens sorted by expert
__device__ int   g_start[LEXP + 1];                          // expert segment starts

__device__ __forceinline__ float tf32_rn(float f) {
    uint32_t u;
    asm("cvt.rna.tf32.f32 %0, %1;" : "=r"(u) : "f"(f));
    return __uint_as_float(u);
}

// ---------------- kernel 1: bucket tokens by expert + zero xa ----------------
__global__ __launch_bounds__(1024) void sort_kernel(const void* idx_raw) {
    __shared__ int cnt[LEXP];
    __shared__ int base[LEXP];
    __shared__ int is64;
    int tid = threadIdx.x;
    if (tid < LEXP) cnt[tid] = 0;
    if (tid == 0) is64 = 1;
    __syncthreads();

    // sniff int32 vs int64: if int64 (values in [0,16)), every odd 32-bit word is 0
    const int* a32 = (const int*)idx_raw;
    for (int j = tid; j < 1024; j += blockDim.x)
        if (a32[2 * j + 1] != 0) is64 = 0;   // benign race
    __syncthreads();
    const long long* a64 = (const long long*)idx_raw;
    int use64 = is64;

    for (int t = tid; t < T_TOK; t += blockDim.x) {
        int l = use64 ? (int)a64[t] : a32[t];
        atomicAdd(&cnt[l], 1);
    }
    __syncthreads();
    if (tid == 0) {
        int s = 0;
        for (int l = 0; l < LEXP; ++l) { base[l] = s; g_start[l] = s; s += cnt[l]; }
        g_start[LEXP] = s;
    }
    __syncthreads();
    for (int t = tid; t < T_TOK; t += blockDim.x) {
        int l = use64 ? (int)a64[t] : a32[t];
        int p = atomicAdd(&base[l], 1);
        g_tok[p] = t;
    }
    for (int i = tid; i < T_TOK * 32; i += blockDim.x) g_xa[i] = 0.0f;
}

// ---------------- kernel 2: round x and W to tf32 (RN) ----------------
__global__ __launch_bounds__(256) void round_kernel(const float4* __restrict__ x,
                                                    const float4* __restrict__ W) {
    const size_t nx = (size_t)T_TOK * DDIM / 4;
    const size_t nw = (size_t)NOUT * DDIM / 4;
    float4* ox = (float4*)g_xr;
    float4* ow = (float4*)g_wr;
    size_t stride = (size_t)gridDim.x * blockDim.x;
    for (size_t i = (size_t)blockIdx.x * blockDim.x + threadIdx.x; i < nx + nw; i += stride) {
        float4 v;
        float4* dst;
        if (i < nx) { v = x[i]; dst = ox + i; }
        else        { v = W[i - nx]; dst = ow + (i - nx); }
        v.x = tf32_rn(v.x); v.y = tf32_rn(v.y);
        v.z = tf32_rn(v.z); v.w = tf32_rn(v.w);
        *dst = v;
    }
}

// ---------------- kernel 3: xa[t, j] = sum_d x[t,d] * A[l, d, j] ----------------
// grid: (16 d-chunks of 128, 16 experts), 512 threads (16 warps, warp = one token)
__global__ __launch_bounds__(512) void xa_kernel(const float* __restrict__ x,
                                                 const float* __restrict__ A) {
    __shared__ float As[128 * 32];   // A[l, d0:d0+128, 0:32]
    int l = blockIdx.y;
    int d0 = blockIdx.x * 128;
    int tid = threadIdx.x;
    int lane = tid & 31, w = tid >> 5;

    size_t abase = ((size_t)l * DDIM + d0) * 32;
    for (int i = tid; i < 128 * 32; i += 512) As[i] = A[abase + i];
    __syncthreads();

    int pbeg = g_start[l], pend = g_start[l + 1];
    for (int p = pbeg + w; p < pend; p += 16) {
        int t = g_tok[p];
        float xv[4];
#pragma unroll
        for (int s = 0; s < 4; ++s)
            xv[s] = x[(size_t)t * DDIM + d0 + s * 32 + lane];
        float acc = 0.0f;
#pragma unroll
        for (int s = 0; s < 4; ++s) {
#pragma unroll
            for (int i = 0; i < 32; ++i) {
                float xb = __shfl_sync(0xffffffffu, xv[s], i);
                acc += xb * As[(s * 32 + i) * 32 + lane];
            }
        }
        atomicAdd(&g_xa[t * 32 + lane], acc);
    }
}

// ---------------- kernel 4: out[t, n] = sum_r xa[t, half*16+r] * B[l, r, n] ----------------
// grid: (22 n-tiles of 512, 16 experts), 256 threads. Fully initializes d_out.
__global__ __launch_bounds__(256) void delta_kernel(const float* __restrict__ B,
                                                    float* __restrict__ out) {
    __shared__ float Bs[16 * 512];
    __shared__ float xs[16];
    int l = blockIdx.y;
    int n0 = blockIdx.x * 512;
    int half = (n0 >= HALF_B) ? 1 : 0;
    int tid = threadIdx.x;

    for (int i = tid; i < 16 * 512; i += 256) {
        int r = i >> 9, c = i & 511;
        Bs[i] = B[((size_t)l * 16 + r) * NOUT + n0 + c];
    }
    __syncthreads();

    const float2* Bv = (const float2*)Bs;
    int pbeg = g_start[l], pend = g_start[l + 1];
    for (int p = pbeg; p < pend; ++p) {
        int t = g_tok[p];
        if (tid < 16) xs[tid] = g_xa[t * 32 + half * 16 + tid];
        __syncthreads();
        float2 acc = make_float2(0.0f, 0.0f);
#pragma unroll
        for (int r = 0; r < 16; ++r) {
            float xr = xs[r];
            float2 bv = Bv[r * 256 + tid];
            acc.x += xr * bv.x;
            acc.y += xr * bv.y;
        }
        *(float2*)(out + (size_t)t * NOUT + n0 + 2 * tid) = acc;
        __syncthreads();
    }
}

// ---------------- kernel 5: main GEMM (tf32 mma.sync), out += x @ W.T ----------------
#define BM 128
#define BN 128
#define BK 32
#define PAD 36     // smem row stride in floats (conflict-free frag loads)

__device__ __forceinline__ void cpa16(uint32_t s, const void* g) {
    asm volatile("cp.async.cg.shared.global [%0], [%1], 16;\n" :: "r"(s), "l"(g));
}
__device__ __forceinline__ void cpa_commit() {
    asm volatile("cp.async.commit_group;\n");
}

__global__ __launch_bounds__(256, 1) void gemm_kernel(float* __restrict__ out) {
    extern __shared__ float smem[];
    float* As = smem;                    // 2 buffers of BM*PAD
    float* Bs = smem + 2 * BM * PAD;     // 2 buffers of BN*PAD

    int tid = threadIdx.x;
    int lane = tid & 31;
    int warp = tid >> 5;
    int warpM = warp & 3;    // 4 warps in M  -> 32 rows each
    int warpN = warp >> 2;   // 2 warps in N  -> 64 cols each
    int grp = lane >> 2;     // 0..7
    int qid = lane & 3;      // 0..3

    int bm = blockIdx.x;     // 0..15
    int bn = blockIdx.y;     // 0..87

    const float* gA = g_xr + (size_t)(bm * BM) * DDIM;
    const float* gB = g_wr + (size_t)(bn * BN) * DDIM;

    // load mapping: 1024 float4 per tile, 4 per thread; seg constant per thread
    int rbase = tid >> 3;      // 0..31
    int seg = tid & 7;       // 0..7

    uint32_t sA = (uint32_t)__cvta_generic_to_shared(As);
    uint32_t sB = (uint32_t)__cvta_generic_to_shared(Bs);

    float c[2][8][4];
#pragma unroll
    for (int mt = 0; mt < 2; ++mt)
#pragma unroll
        for (int nt = 0; nt < 8; ++nt)
#pragma unroll
            for (int i = 0; i < 4; ++i) c[mt][nt][i] = 0.0f;

    auto loadTiles = [&](int buf, int k0) {
        uint32_t aoff = sA + (uint32_t)(buf * BM * PAD) * 4u;
        uint32_t boff = sB + (uint32_t)(buf * BN * PAD) * 4u;
#pragma unroll
        for (int i = 0; i < 4; ++i) {
            int row = rbase + i * 32;
            cpa16(aoff + (uint32_t)(row * PAD + seg * 4) * 4u,
                  gA + (size_t)row * DDIM + k0 + seg * 4);
            cpa16(boff + (uint32_t)(row * PAD + seg * 4) * 4u,
                  gB + (size_t)row * DDIM + k0 + seg * 4);
        }
    };

    loadTiles(0, 0);
    cpa_commit();

    const int NITER = DDIM / BK;   // 64
#pragma unroll 1
    for (int it = 0; it < NITER; ++it) {
        if (it < NITER - 1) {
            loadTiles((it + 1) & 1, (it + 1) * BK);
            cpa_commit();
            asm volatile("cp.async.wait_group 1;\n");
        } else {
            asm volatile("cp.async.wait_group 0;\n");
        }
        __syncthreads();

        int buf = it & 1;
        const uint32_t* AsU = (const uint32_t*)(As + buf * BM * PAD);
        const uint32_t* BsU = (const uint32_t*)(Bs + buf * BN * PAD);
        int aRow = warpM * 32 + grp;
        int bRow = warpN * 64 + grp;

#pragma unroll
        for (int ks = 0; ks < 4; ++ks) {
            int kb = ks * 8 + qid;
            uint32_t a[2][4], b[8][2];
#pragma unroll
            for (int mt = 0; mt < 2; ++mt) {
                const uint32_t* p = AsU + (aRow + mt * 16) * PAD + kb;
                a[mt][0] = p[0];
                a[mt][1] = p[8 * PAD];
                a[mt][2] = p[4];
                a[mt][3] = p[8 * PAD + 4];
            }
#pragma unroll
            for (int nt = 0; nt < 8; ++nt) {
                const uint32_t* p = BsU + (bRow + nt * 8) * PAD + kb;
                b[nt][0] = p[0];
                b[nt][1] = p[4];
            }
#pragma unroll
            for (int mt = 0; mt < 2; ++mt) {
#pragma unroll
                for (int nt = 0; nt < 8; ++nt) {
                    asm volatile(
                        "mma.sync.aligned.m16n8k8.row.col.f32.tf32.tf32.f32 "
                        "{%0,%1,%2,%3}, {%4,%5,%6,%7}, {%8,%9}, {%0,%1,%2,%3};\n"
                        : "+f"(c[mt][nt][0]), "+f"(c[mt][nt][1]),
                          "+f"(c[mt][nt][2]), "+f"(c[mt][nt][3])
                        : "r"(a[mt][0]), "r"(a[mt][1]), "r"(a[mt][2]), "r"(a[mt][3]),
                          "r"(b[nt][0]), "r"(b[nt][1]));
                }
            }
        }
        __syncthreads();
    }

    // epilogue: out += acc (out already holds delta)
#pragma unroll
    for (int mt = 0; mt < 2; ++mt) {
#pragma unroll
        for (int nt = 0; nt < 8; ++nt) {
            int r = bm * BM + warpM * 32 + mt * 16 + grp;
            int col = bn * BN + warpN * 64 + nt * 8 + qid * 2;
            size_t o = (size_t)r * NOUT + col;
            float2* p0 = (float2*)(out + o);
            float2 v0 = *p0;
            v0.x += c[mt][nt][0];
            v0.y += c[mt][nt][1];
            *p0 = v0;
            float2* p1 = (float2*)(out + o + (size_t)8 * NOUT);
            float2 v1 = *p1;
            v1.x += c[mt][nt][2];
            v1.y += c[mt][nt][3];
            *p1 = v1;
        }
    }
}

// ---------------- launch ----------------
extern "C" void kernel_launch(void* const* d_in, const int* in_sizes, int n_in,
                              void* d_out, int out_size) {
    const float* x = (const float*)d_in[0];
    const float* W = (const float*)d_in[1];
    const float* A = (const float*)d_in[2];
    const float* B = (const float*)d_in[3];
    const void*  idx = d_in[4];
    float* out = (float*)d_out;

    (void)in_sizes; (void)n_in; (void)out_size;

    const int SMEM_GEMM = 2 * (BM * PAD + BN * PAD) * 4;   // 73728 bytes
    cudaFuncSetAttribute(gemm_kernel, cudaFuncAttributeMaxDynamicSharedMemorySize, SMEM_GEMM);

    sort_kernel<<<1, 1024>>>(idx);
    round_kernel<<<2048, 256>>>((const float4*)x, (const float4*)W);
    xa_kernel<<<dim3(16, 16), 512>>>(x, A);
    delta_kernel<<<dim3(22, 16), 256>>>(B, out);
    gemm_kernel<<<dim3(16, 88), 256, SMEM_GEMM>>>(out);
}

// round 5
// speedup vs baseline: 1.1416x; 1.1416x over previous
#include <cuda_runtime.h>
#include <cstdint>

#define T_TOK 2048
#define DDIM  2048
#define NOUT  11264
#define LEXP  16
#define HALF_B 5632

// ---------------- scratch (device globals: allocation-free) ----------------
__device__ __align__(16) float g_xr[(size_t)T_TOK * DDIM];   // tf32-rounded x
__device__ __align__(16) float g_wr[(size_t)NOUT * DDIM];    // tf32-rounded W
__device__ float g_xa[T_TOK * 32];                           // xa = x . A[l]
__device__ int   g_tok[T_TOK];                               // tokens sorted by expert
__device__ int   g_start[LEXP + 1];                          // expert segment starts

__device__ __forceinline__ float tf32_rn(float f) {
    uint32_t u;
    asm("cvt.rna.tf32.f32 %0, %1;" : "=r"(u) : "f"(f));
    return __uint_as_float(u);
}

// ---------------- kernel 1: bucket tokens by expert + zero xa ----------------
__global__ __launch_bounds__(1024) void sort_kernel(const void* idx_raw) {
    __shared__ int cnt[LEXP];
    __shared__ int base[LEXP];
    __shared__ int is64;
    int tid = threadIdx.x;
    if (tid < LEXP) cnt[tid] = 0;
    if (tid == 0) is64 = 1;
    __syncthreads();

    // sniff int32 vs int64: if int64 (values in [0,16)), every odd 32-bit word is 0
    const int* a32 = (const int*)idx_raw;
    for (int j = tid; j < 1024; j += blockDim.x)
        if (a32[2 * j + 1] != 0) is64 = 0;   // benign race
    __syncthreads();
    const long long* a64 = (const long long*)idx_raw;
    int use64 = is64;

    for (int t = tid; t < T_TOK; t += blockDim.x) {
        int l = use64 ? (int)a64[t] : a32[t];
        atomicAdd(&cnt[l], 1);
    }
    __syncthreads();
    if (tid == 0) {
        int s = 0;
        for (int l = 0; l < LEXP; ++l) { base[l] = s; g_start[l] = s; s += cnt[l]; }
        g_start[LEXP] = s;
    }
    __syncthreads();
    for (int t = tid; t < T_TOK; t += blockDim.x) {
        int l = use64 ? (int)a64[t] : a32[t];
        int p = atomicAdd(&base[l], 1);
        g_tok[p] = t;
    }
    for (int i = tid; i < T_TOK * 32; i += blockDim.x) g_xa[i] = 0.0f;
}

// ---------------- kernel 2: round x and W to tf32 (RN) ----------------
__global__ __launch_bounds__(256) void round_kernel(const float4* __restrict__ x,
                                                    const float4* __restrict__ W) {
    const size_t nx = (size_t)T_TOK * DDIM / 4;
    const size_t nw = (size_t)NOUT * DDIM / 4;
    float4* ox = (float4*)g_xr;
    float4* ow = (float4*)g_wr;
    size_t stride = (size_t)gridDim.x * blockDim.x;
    for (size_t i = (size_t)blockIdx.x * blockDim.x + threadIdx.x; i < nx + nw; i += stride) {
        float4 v;
        float4* dst;
        if (i < nx) { v = x[i]; dst = ox + i; }
        else        { v = W[i - nx]; dst = ow + (i - nx); }
        v.x = tf32_rn(v.x); v.y = tf32_rn(v.y);
        v.z = tf32_rn(v.z); v.w = tf32_rn(v.w);
        *dst = v;
    }
}

// ---------------- kernel 3: xa[t, j] = sum_d x[t,d] * A[l, d, j] ----------------
// grid: (16 d-chunks of 128, 16 experts), 512 threads (16 warps, warp = one token)
__global__ __launch_bounds__(512) void xa_kernel(const float* __restrict__ x,
                                                 const float* __restrict__ A) {
    __shared__ float As[128 * 32];   // A[l, d0:d0+128, 0:32]
    int l = blockIdx.y;
    int d0 = blockIdx.x * 128;
    int tid = threadIdx.x;
    int lane = tid & 31, w = tid >> 5;

    size_t abase = ((size_t)l * DDIM + d0) * 32;
    for (int i = tid; i < 128 * 32; i += 512) As[i] = A[abase + i];
    __syncthreads();

    int pbeg = g_start[l], pend = g_start[l + 1];
    for (int p = pbeg + w; p < pend; p += 16) {
        int t = g_tok[p];
        float xv[4];
#pragma unroll
        for (int s = 0; s < 4; ++s)
            xv[s] = x[(size_t)t * DDIM + d0 + s * 32 + lane];
        float acc = 0.0f;
#pragma unroll
        for (int s = 0; s < 4; ++s) {
#pragma unroll
            for (int i = 0; i < 32; ++i) {
                float xb = __shfl_sync(0xffffffffu, xv[s], i);
                acc += xb * As[(s * 32 + i) * 32 + lane];
            }
        }
        atomicAdd(&g_xa[t * 32 + lane], acc);
    }
}

// ---------------- kernel 4: delta -> out (full init), sync-free token loop ----
__global__ __launch_bounds__(256) void delta_kernel(const float* __restrict__ B,
                                                    float* __restrict__ out) {
    __shared__ float Bs[16 * 512];
    int l = blockIdx.y;
    int n0 = blockIdx.x * 512;
    int half = (n0 >= HALF_B) ? 1 : 0;
    int tid = threadIdx.x;

    for (int i = tid; i < 16 * 512; i += 256) {
        int r = i >> 9, c = i & 511;
        Bs[i] = B[((size_t)l * 16 + r) * NOUT + n0 + c];
    }
    __syncthreads();

    const float2* Bv = (const float2*)Bs;
    int pbeg = g_start[l], pend = g_start[l + 1];
    for (int p = pbeg; p < pend; ++p) {
        int t = g_tok[p];
        const float* xa = g_xa + t * 32 + half * 16;
        float2 acc = make_float2(0.0f, 0.0f);
#pragma unroll
        for (int r = 0; r < 16; ++r) {
            float xr = __ldg(xa + r);             // warp-uniform broadcast, L1-hit
            float2 bv = Bv[r * 256 + tid];
            acc.x += xr * bv.x;
            acc.y += xr * bv.y;
        }
        *(float2*)(out + (size_t)t * NOUT + n0 + 2 * tid) = acc;
    }
}

// ---------------- kernel 5: main GEMM (tf32 mma.sync), out += x @ W.T ----------------
#define BM 128
#define BN 128
#define BK 32
#define PAD 36                         // smem row stride in floats
#define STAGES 3
#define STAGE_FLOATS ((BM + BN) * PAD) // 9216 floats = 36864 B per stage
#define SMEM_GEMM (STAGES * STAGE_FLOATS * 4)   // 110592 B

__device__ __forceinline__ void cpa16(uint32_t s, const void* g) {
    asm volatile("cp.async.cg.shared.global [%0], [%1], 16;\n" :: "r"(s), "l"(g));
}

__global__ __launch_bounds__(256, 2) void gemm_kernel(float* __restrict__ out) {
    extern __shared__ float smem[];

    int tid = threadIdx.x;
    int lane = tid & 31;
    int warp = tid >> 5;
    int warpM = warp & 3;    // 4 warps in M  -> 32 rows each
    int warpN = warp >> 2;   // 2 warps in N  -> 64 cols each
    int grp = lane >> 2;     // 0..7
    int qid = lane & 3;      // 0..3

    int bm = blockIdx.x;     // 0..15
    int bn = blockIdx.y;     // 0..87

    const float* gA = g_xr + (size_t)(bm * BM) * DDIM;
    const float* gB = g_wr + (size_t)(bn * BN) * DDIM;

    // load mapping: 1024 float4 per (A+B) tile pair, 8 per thread
    int rbase = tid >> 3;    // 0..31
    int seg = tid & 7;       // 0..7

    uint32_t sBase = (uint32_t)__cvta_generic_to_shared(smem);

    float c[2][8][4];
#pragma unroll
    for (int mt = 0; mt < 2; ++mt)
#pragma unroll
        for (int nt = 0; nt < 8; ++nt)
#pragma unroll
            for (int i = 0; i < 4; ++i) c[mt][nt][i] = 0.0f;

    auto loadTiles = [&](int buf, int k0) {
        uint32_t aoff = sBase + (uint32_t)(buf * STAGE_FLOATS) * 4u;
        uint32_t boff = aoff + (uint32_t)(BM * PAD) * 4u;
#pragma unroll
        for (int i = 0; i < 4; ++i) {
            int row = rbase + i * 32;
            cpa16(aoff + (uint32_t)(row * PAD + seg * 4) * 4u,
                  gA + (size_t)row * DDIM + k0 + seg * 4);
            cpa16(boff + (uint32_t)(row * PAD + seg * 4) * 4u,
                  gB + (size_t)row * DDIM + k0 + seg * 4);
        }
        asm volatile("cp.async.commit_group;\n");
    };

    loadTiles(0, 0);
    loadTiles(1, BK);

    const int NITER = DDIM / BK;   // 64
#pragma unroll 1
    for (int it = 0; it < NITER; ++it) {
        if (it < NITER - 1) {
            asm volatile("cp.async.wait_group 1;\n");
        } else {
            asm volatile("cp.async.wait_group 0;\n");
        }
        __syncthreads();
        // safe now: every thread finished computing on buf (it-1)%3 == (it+2)%3
        if (it + 2 < NITER) {
            int nbuf = (it + 2) % STAGES;
            loadTiles(nbuf, (it + 2) * BK);
        }

        int buf = it % STAGES;
        const uint32_t* AsU = (const uint32_t*)(smem + buf * STAGE_FLOATS);
        const uint32_t* BsU = AsU + BM * PAD;
        int aRow = warpM * 32 + grp;
        int bRow = warpN * 64 + grp;

#pragma unroll
        for (int ks = 0; ks < 4; ++ks) {
            int kb = ks * 8 + qid;
            uint32_t a[2][4], b[8][2];
#pragma unroll
            for (int mt = 0; mt < 2; ++mt) {
                const uint32_t* p = AsU + (aRow + mt * 16) * PAD + kb;
                a[mt][0] = p[0];
                a[mt][1] = p[8 * PAD];
                a[mt][2] = p[4];
                a[mt][3] = p[8 * PAD + 4];
            }
#pragma unroll
            for (int nt = 0; nt < 8; ++nt) {
                const uint32_t* p = BsU + (bRow + nt * 8) * PAD + kb;
                b[nt][0] = p[0];
                b[nt][1] = p[4];
            }
#pragma unroll
            for (int mt = 0; mt < 2; ++mt) {
#pragma unroll
                for (int nt = 0; nt < 8; ++nt) {
                    asm volatile(
                        "mma.sync.aligned.m16n8k8.row.col.f32.tf32.tf32.f32 "
                        "{%0,%1,%2,%3}, {%4,%5,%6,%7}, {%8,%9}, {%0,%1,%2,%3};\n"
                        : "+f"(c[mt][nt][0]), "+f"(c[mt][nt][1]),
                          "+f"(c[mt][nt][2]), "+f"(c[mt][nt][3])
                        : "r"(a[mt][0]), "r"(a[mt][1]), "r"(a[mt][2]), "r"(a[mt][3]),
                          "r"(b[nt][0]), "r"(b[nt][1]));
                }
            }
        }
    }

    // epilogue: out += acc (out already holds delta)
#pragma unroll
    for (int mt = 0; mt < 2; ++mt) {
#pragma unroll
        for (int nt = 0; nt < 8; ++nt) {
            int r = bm * BM + warpM * 32 + mt * 16 + grp;
            int col = bn * BN + warpN * 64 + nt * 8 + qid * 2;
            size_t o = (size_t)r * NOUT + col;
            float2* p0 = (float2*)(out + o);
            float2 v0 = *p0;
            v0.x += c[mt][nt][0];
            v0.y += c[mt][nt][1];
            *p0 = v0;
            float2* p1 = (float2*)(out + o + (size_t)8 * NOUT);
            float2 v1 = *p1;
            v1.x += c[mt][nt][2];
            v1.y += c[mt][nt][3];
            *p1 = v1;
        }
    }
}

// ---------------- launch ----------------
extern "C" void kernel_launch(void* const* d_in, const int* in_sizes, int n_in,
                              void* d_out, int out_size) {
    const float* x = (const float*)d_in[0];
    const float* W = (const float*)d_in[1];
    const float* A = (const float*)d_in[2];
    const float* B = (const float*)d_in[3];
    const void*  idx = d_in[4];
    float* out = (float*)d_out;

    (void)in_sizes; (void)n_in; (void)out_size;

    cudaFuncSetAttribute(gemm_kernel, cudaFuncAttributeMaxDynamicSharedMemorySize, SMEM_GEMM);

    sort_kernel<<<1, 1024>>>(idx);
    round_kernel<<<2048, 256>>>((const float4*)x, (const float4*)W);
    xa_kernel<<<dim3(16, 16), 512>>>(x, A);
    delta_kernel<<<dim3(22, 16), 256>>>(B, out);
    gemm_kernel<<<dim3(16, 88), 256, SMEM_GEMM>>>(out);
}